// round 16
// baseline (speedup 1.0000x reference)
#include <cuda_runtime.h>
#include <cstdint>

// ---------------------------------------------------------------------------
// RNN_57208964382771: Elman RNN (tanh), B=64, T=2048, H=8, V=O=1000
// R16 = R14 (proven: speculative time-segmentation, bit-exact) +
//       in-thread 4-row load batching in projection pass 2 (MLP 1 -> 8).
//       (R15's SMEM staging is REVERTED: it broke correctness.)
//   blocks [0, B)    : recurrence, 4 warps = 4 segments of sequence b
//                      (WARM=256 discarded steps for seg>0). Then join proj pool.
//   blocks [B, 148)  : projection (masked pass, then live pass).
// ---------------------------------------------------------------------------

#define HH     8
#define MAX_B  64
#define MAX_T  2048
#define MAX_V  1000
#define CH     64
#define SEG    4
#define WARM   256
#define GRID   148

__device__ float g_hs[(size_t)MAX_B * MAX_T * HH];
__device__ int   g_flags[MAX_B * SEG];     // chunks published per (b, seg)

__device__ __forceinline__ float fast_tanh(float x)
{
    float y;
    asm("tanh.approx.f32 %0, %1;" : "=f"(y) : "f"(x));
    return y;
}

__device__ __forceinline__ int load_acquire_gpu(const int* p)
{
    int v;
    asm volatile("ld.acquire.gpu.global.s32 %0, [%1];" : "=r"(v) : "l"(p) : "memory");
    return v;
}

__device__ __forceinline__ void store_cs(float* p, float4 v)
{
    asm volatile("st.global.cs.v4.f32 [%0], {%1,%2,%3,%4};"
                 :: "l"(p), "f"(v.x), "f"(v.y), "f"(v.z), "f"(v.w) : "memory");
}

__device__ __forceinline__ float4 proj_row(const float4 ha, const float4 hb,
                                           const float (&w)[4][HH], const float4 bias)
{
    const float hh[HH] = {ha.x, ha.y, ha.z, ha.w, hb.x, hb.y, hb.z, hb.w};
    float a0 = bias.x, a1 = bias.y, a2 = bias.z, a3 = bias.w;
#pragma unroll
    for (int h = 0; h < HH; h++) {
        a0 = fmaf(w[0][h], hh[h], a0);
        a1 = fmaf(w[1][h], hh[h], a1);
        a2 = fmaf(w[2][h], hh[h], a2);
        a3 = fmaf(w[3][h], hh[h], a3);
    }
    float4 acc; acc.x = a0; acc.y = a1; acc.z = a2; acc.w = a3;
    return acc;
}

extern __shared__ char dsmem[];

// ---- projection worker: both block roles end up here (all 256 threads) ----
__device__ __forceinline__ void proj_worker(int worker,
                                            const float* __restrict__ W_out,
                                            const float* __restrict__ b_out,
                                            const void* __restrict__ lengthsv,
                                            float* __restrict__ out,
                                            int B, int T, int O, int LC)
{
    const int tid  = threadIdx.x;
    const int nvec = O >> 2;                    // 250

    // lengths dtype: values >= 1, so int32 data has nonzero odd words
    const int* l32 = (const int*)lengthsv;
    int nzl = 0;
    for (int k = 1; k < B; k += 2) nzl |= (l32[k] != 0);
    const int is64l = !nzl;

    float w[4][HH];
    float4 bias = make_float4(0.f, 0.f, 0.f, 0.f);
    if (tid < nvec) {
#pragma unroll
        for (int k = 0; k < 4; k++) {
            const int o = tid * 4 + k;
#pragma unroll
            for (int h = 0; h < HH; h++)
                w[k][h] = W_out[o * HH + h];
        }
        bias = *(const float4*)(b_out + tid * 4);
    }

    const int ntiles = B * SEG * LC;

    // ---- pass 1: fully masked tiles (no dependency, pure store stream) ----
    for (int tl = worker; tl < ntiles; tl += GRID) {
        const int cc  = tl / (SEG * B);
        const int r   = tl % (SEG * B);
        const int seg = r / B;
        const int b   = r % B;
        const int t0  = (seg * LC + cc) * CH;
        const int len = is64l ? (int)((const long long*)lengthsv)[b] : l32[b];
        if (len > t0) continue;
        if (tid < nvec) {
            const int rows = min(CH, T - t0);
            float* orow = out + ((size_t)b * T + t0) * O + tid * 4;
#pragma unroll 4
            for (int rr = 0; rr < rows; rr++)
                store_cs(orow + (size_t)rr * O, bias);
        }
    }

    // ---- pass 2: live tiles, production order, 4-row batched loads ----
    for (int tl = worker; tl < ntiles; tl += GRID) {
        const int cc  = tl / (SEG * B);
        const int r   = tl % (SEG * B);
        const int seg = r / B;
        const int b   = r % B;
        const int t0  = (seg * LC + cc) * CH;
        const int len = is64l ? (int)((const long long*)lengthsv)[b] : l32[b];
        if (len <= t0) continue;

        if (tid == 0) {
            while (load_acquire_gpu(&g_flags[b * SEG + seg]) <= cc) __nanosleep(64);
        }
        __syncthreads();

        if (tid < nvec) {
            const int rows = min(CH, T - t0);
            const int rlim = min(rows, len - t0);
            const float4* hsv = (const float4*)(g_hs + ((size_t)b * T + t0) * HH);
            float* orow = out + ((size_t)b * T + t0) * O + tid * 4;

            int rr = 0;
            for (; rr + 4 <= rlim; rr += 4) {
                // MLP=8: all loads issued before any consumption
                const float4 ha0 = __ldg(hsv + (rr + 0) * 2);
                const float4 hb0 = __ldg(hsv + (rr + 0) * 2 + 1);
                const float4 ha1 = __ldg(hsv + (rr + 1) * 2);
                const float4 hb1 = __ldg(hsv + (rr + 1) * 2 + 1);
                const float4 ha2 = __ldg(hsv + (rr + 2) * 2);
                const float4 hb2 = __ldg(hsv + (rr + 2) * 2 + 1);
                const float4 ha3 = __ldg(hsv + (rr + 3) * 2);
                const float4 hb3 = __ldg(hsv + (rr + 3) * 2 + 1);

                store_cs(orow + (size_t)(rr + 0) * O, proj_row(ha0, hb0, w, bias));
                store_cs(orow + (size_t)(rr + 1) * O, proj_row(ha1, hb1, w, bias));
                store_cs(orow + (size_t)(rr + 2) * O, proj_row(ha2, hb2, w, bias));
                store_cs(orow + (size_t)(rr + 3) * O, proj_row(ha3, hb3, w, bias));
            }
            for (; rr < rlim; rr++) {
                const float4 ha = __ldg(hsv + rr * 2);
                const float4 hb = __ldg(hsv + rr * 2 + 1);
                store_cs(orow + (size_t)rr * O, proj_row(ha, hb, w, bias));
            }
#pragma unroll 4
            for (; rr < rows; rr++)
                store_cs(orow + (size_t)rr * O, bias);
        }
    }
}

__global__ void __launch_bounds__(256, 1)
rnn_fused_kernel(const void* __restrict__ Xv,
                 const void* __restrict__ lengthsv,
                 const float* __restrict__ emb,
                 const float* __restrict__ W_ih,
                 const float* __restrict__ W_hh,
                 const float* __restrict__ b_ih,
                 const float* __restrict__ b_hh,
                 const float* __restrict__ W_out,
                 const float* __restrict__ b_out,
                 float* __restrict__ out,
                 int B, int T, int V, int O, int tail)
{
    const int bid = blockIdx.x;
    const int tid = threadIdx.x;
    const int L   = T / SEG;            // 512
    const int LC  = L / CH;             // 8 chunks per segment

    if (bid < B) {
        // =================== recurrence role (seq b = bid) ===================
        float* s_embproj = (float*)dsmem;                   // V*HH floats
        int*   s_tok     = (int*)(dsmem + MAX_V * HH * 4);  // T+2 ints
        __shared__ int s_is64;

        {   // inline dtype detect on X: int64 (<2^31) => odd words all zero
            const int* x32 = (const int*)Xv;
            const int pairs = min(1024, (B * T) >> 1);
            int nz = 0;
            for (int i = tid; i < pairs; i += blockDim.x)
                nz |= (x32[2 * i + 1] != 0);
            const int any = __syncthreads_or(nz);
            if (tid == 0) s_is64 = !any;
            __syncthreads();
        }
        const int is64 = s_is64;

        // --- stage this sequence's full token stream ---
        if (is64) {
            const long long* X = (const long long*)Xv;
            for (int t = tid; t < T; t += blockDim.x) {
                int v = (int)X[(long long)bid * T + t];
                s_tok[t] = min(max(v, 0), V - 1);
            }
        } else {
            const int* X = (const int*)Xv;
            for (int t = tid; t < T; t += blockDim.x) {
                int v = X[bid * T + t];
                s_tok[t] = min(max(v, 0), V - 1);
            }
        }
        if (tid < 2) s_tok[T + tid] = 0;

        // --- embedding projection with both biases folded in ---
        for (int v = tid; v < V; v += blockDim.x) {
            float e[HH];
#pragma unroll
            for (int h = 0; h < HH; h++) e[h] = emb[v * HH + h];
#pragma unroll
            for (int i = 0; i < HH; i++) {
                float s = b_ih[i] + b_hh[i];
#pragma unroll
                for (int h = 0; h < HH; h++)
                    s = fmaf(e[h], W_ih[i * HH + h], s);
                s_embproj[v * HH + i] = s;
            }
        }
        __syncthreads();

        if (tid < SEG * 32) {
            const int seg  = tid >> 5;          // this warp's segment
            const int lane = tid & 31;
            const int i    = lane & 7;

            const float w0 = W_hh[i * HH + 0], w1 = W_hh[i * HH + 1];
            const float w2 = W_hh[i * HH + 2], w3 = W_hh[i * HH + 3];
            const float w4 = W_hh[i * HH + 4], w5 = W_hh[i * HH + 5];
            const float w6 = W_hh[i * HH + 6], w7 = W_hh[i * HH + 7];

            float h0 = 0.f, h1 = 0.f, h2 = 0.f, h3 = 0.f;
            float h4 = 0.f, h5 = 0.f, h6 = 0.f, h7 = 0.f;

            float* __restrict__ hs_out = g_hs + (size_t)bid * T * HH;
            const int* __restrict__ tok = s_tok;

            const int tout = seg * L;                       // first emitted step
            const int tw   = (seg == 0) ? 0 : tout - WARM;  // warmup start

            int   tokB = tok[tw + 1];
            float xp   = s_embproj[tok[tw] * HH + i];

            // ---- warmup: champion step without store ----
#pragma unroll 4
            for (int t = tw; t < tout; t++) {
                const int   tokC = tok[t + 2];
                const float xp_n = s_embproj[tokB * HH + i];
                float a = fmaf(h0, w0, xp);
                a = fmaf(h1, w1, a);
                a = fmaf(h2, w2, a);
                a = fmaf(h3, w3, a);
                float bb = h4 * w4;
                bb = fmaf(h5, w5, bb);
                bb = fmaf(h6, w6, bb);
                bb = fmaf(h7, w7, bb);
                const float y = fast_tanh(a + bb);
                h0 = __shfl_sync(0xffffffffu, y, 0);
                h1 = __shfl_sync(0xffffffffu, y, 1);
                h2 = __shfl_sync(0xffffffffu, y, 2);
                h3 = __shfl_sync(0xffffffffu, y, 3);
                h4 = __shfl_sync(0xffffffffu, y, 4);
                h5 = __shfl_sync(0xffffffffu, y, 5);
                h6 = __shfl_sync(0xffffffffu, y, 6);
                h7 = __shfl_sync(0xffffffffu, y, 7);
                xp   = xp_n;
                tokB = tokC;
            }

            // ---- emit: champion chunk loop with per-chunk publish ----
            for (int cc = 0; cc < LC; cc++) {
                const int t0 = tout + cc * CH;
#pragma unroll 4
                for (int t = t0; t < t0 + CH; t++) {
                    const int   tokC = tok[t + 2];
                    const float xp_n = s_embproj[tokB * HH + i];
                    float a = fmaf(h0, w0, xp);
                    a = fmaf(h1, w1, a);
                    a = fmaf(h2, w2, a);
                    a = fmaf(h3, w3, a);
                    float bb = h4 * w4;
                    bb = fmaf(h5, w5, bb);
                    bb = fmaf(h6, w6, bb);
                    bb = fmaf(h7, w7, bb);
                    const float y = fast_tanh(a + bb);
                    if (lane < HH) hs_out[t * HH + lane] = y;
                    h0 = __shfl_sync(0xffffffffu, y, 0);
                    h1 = __shfl_sync(0xffffffffu, y, 1);
                    h2 = __shfl_sync(0xffffffffu, y, 2);
                    h3 = __shfl_sync(0xffffffffu, y, 3);
                    h4 = __shfl_sync(0xffffffffu, y, 4);
                    h5 = __shfl_sync(0xffffffffu, y, 5);
                    h6 = __shfl_sync(0xffffffffu, y, 6);
                    h7 = __shfl_sync(0xffffffffu, y, 7);
                    xp   = xp_n;
                    tokB = tokC;
                }
                __syncwarp();
                if (lane == 0) {
                    __threadfence();
                    *(volatile int*)&g_flags[bid * SEG + seg] = cc + 1;
                }
            }
        }

        // all warps meet here, then the whole block joins the projection pool
        __syncthreads();
        proj_worker(bid, W_out, b_out, lengthsv, out, B, T, O, LC);
        return;
    }

    // =================== projection-dedicated role ===================
    // tail passthrough handled once by the first proj block
    if (bid == B && tail > 0) {
        const int* l32 = (const int*)lengthsv;
        int nzl = 0;
        for (int k = 1; k < B; k += 2) nzl |= (l32[k] != 0);
        const int is64l = !nzl;
        const long long base = (long long)B * T * O;
        if (tail == 2 * B) {
            if (tid < B) {
                long long lv = is64l ? ((const long long*)lengthsv)[tid]
                                     : (long long)l32[tid];
                ((long long*)(out + base))[tid] = lv;
            }
        } else {
            for (int k = tid; k < tail; k += 256) {
                float v = 0.0f;
                if (k < B)
                    v = (float)(is64l ? ((const long long*)lengthsv)[k]
                                      : (long long)l32[k]);
                out[base + k] = v;
            }
        }
    }

    proj_worker(bid, W_out, b_out, lengthsv, out, B, T, O, LC);
}

extern "C" void kernel_launch(void* const* d_in, const int* in_sizes, int n_in,
                              void* d_out, int out_size)
{
    const void*  X       = d_in[0];
    const void*  lengths = d_in[1];
    const float* emb     = (const float*)d_in[2];
    const float* W_ih    = (const float*)d_in[3];
    const float* W_hh    = (const float*)d_in[4];
    const float* b_ih    = (const float*)d_in[5];
    const float* b_hh    = (const float*)d_in[6];
    const float* W_out   = (const float*)d_in[7];
    const float* b_out   = (const float*)d_in[8];
    float*       out     = (float*)d_out;

    const int B  = in_sizes[1];
    const int BT = in_sizes[0];
    const int T  = BT / B;
    const int H  = in_sizes[5];
    const int V  = in_sizes[2] / H;
    const int O  = in_sizes[8];

    const long long tail = (long long)out_size - (long long)BT * O;

    const int smemBytes = MAX_V * HH * 4 + (MAX_T + 2) * 4;   // ~40 KB dynamic
    cudaFuncSetAttribute(rnn_fused_kernel,
                         cudaFuncAttributeMaxDynamicSharedMemorySize,
                         smemBytes);

    void* flagAddr = nullptr;
    cudaGetSymbolAddress(&flagAddr, g_flags);
    cudaMemsetAsync(flagAddr, 0, sizeof(int) * MAX_B * SEG);

    rnn_fused_kernel<<<GRID, 256, smemBytes>>>(X, lengths, emb, W_ih, W_hh,
                                               b_ih, b_hh, W_out, b_out, out,
                                               B, T, V, O,
                                               (int)(tail > 0 ? tail : 0));
}

// round 17
// speedup vs baseline: 1.2392x; 1.2392x over previous
#include <cuda_runtime.h>
#include <cstdint>

// ---------------------------------------------------------------------------
// RNN_57208964382771: Elman RNN (tanh), B=64, T=2048, H=8, V=O=1000
// R17: per-SM store throughput (~29GB/s/SM) is the binder. Keep all 148 SMs
// storing from t=0:
//   * every block = two 128-thread proj TEAMS (thread covers cols j, j+128)
//   * rec blocks (bid<64): warps 0-3 run the bit-exact R14 recurrence
//     (SEG=4, WARM=256), warps 4-7 project IMMEDIATELY; rec warps join after.
//   * atomic-ticket dispatch (masked counter, then live counter) balances
//     late-joining teams automatically.
//   * teams sync via named barriers only; flag waits are per-thread acquire
//     spins. Producers never wait -> no deadlock.
// ---------------------------------------------------------------------------

#define HH     8
#define MAX_B  64
#define MAX_T  2048
#define MAX_V  1000
#define CH     64
#define SEG    4
#define WARM   256
#define GRID   148

__device__ float g_hs[(size_t)MAX_B * MAX_T * HH];
__device__ int   g_flags[MAX_B * SEG];   // chunks published per (b, seg)
__device__ int   g_tkt[2];               // tile tickets: [0]=masked pass, [1]=live pass

__device__ __forceinline__ float fast_tanh(float x)
{
    float y;
    asm("tanh.approx.f32 %0, %1;" : "=f"(y) : "f"(x));
    return y;
}

__device__ __forceinline__ int load_acquire_gpu(const int* p)
{
    int v;
    asm volatile("ld.acquire.gpu.global.s32 %0, [%1];" : "=r"(v) : "l"(p) : "memory");
    return v;
}

__device__ __forceinline__ void store_cs(float* p, float4 v)
{
    asm volatile("st.global.cs.v4.f32 [%0], {%1,%2,%3,%4};"
                 :: "l"(p), "f"(v.x), "f"(v.y), "f"(v.z), "f"(v.w) : "memory");
}

__device__ __forceinline__ void team_bar(int id)
{
    asm volatile("bar.sync %0, %1;" :: "r"(id), "r"(128) : "memory");
}

__device__ __forceinline__ float4 proj_row4(const float4 ha, const float4 hb,
                                            const float (&w)[4][HH], const float4 bias)
{
    const float hh[HH] = {ha.x, ha.y, ha.z, ha.w, hb.x, hb.y, hb.z, hb.w};
    float a0 = bias.x, a1 = bias.y, a2 = bias.z, a3 = bias.w;
#pragma unroll
    for (int h = 0; h < HH; h++) {
        a0 = fmaf(w[0][h], hh[h], a0);
        a1 = fmaf(w[1][h], hh[h], a1);
        a2 = fmaf(w[2][h], hh[h], a2);
        a3 = fmaf(w[3][h], hh[h], a3);
    }
    float4 acc; acc.x = a0; acc.y = a1; acc.z = a2; acc.w = a3;
    return acc;
}

extern __shared__ char dsmem[];

// ---- 128-thread projection team; autonomous (named barrier + flag spins) ----
__device__ void proj_team(const float* __restrict__ W_out,
                          const float* __restrict__ b_out,
                          const void* __restrict__ lengthsv,
                          float* __restrict__ out,
                          int B, int T, int O, int LC,
                          volatile int* s_tk)
{
    const int tid   = threadIdx.x;
    const int slot  = tid >> 7;          // 0 or 1
    const int j     = tid & 127;         // column group
    const int barid = 1 + slot;
    const int nvec  = O >> 2;            // 250
    const bool two  = (j + 128) < nvec;  // j < 122

    // lengths dtype: values >= 1, so int32 data has nonzero odd words
    const int* l32 = (const int*)lengthsv;
    int nzl = 0;
    for (int k = 1; k < B; k += 2) nzl |= (l32[k] != 0);
    const int is64l = !nzl;

    float w1[4][HH], w2[4][HH];
    float4 bias1, bias2;
#pragma unroll
    for (int k = 0; k < 4; k++)
#pragma unroll
        for (int h = 0; h < HH; h++)
            w1[k][h] = W_out[(j * 4 + k) * HH + h];
    bias1 = *(const float4*)(b_out + j * 4);
    if (two) {
#pragma unroll
        for (int k = 0; k < 4; k++)
#pragma unroll
            for (int h = 0; h < HH; h++)
                w2[k][h] = W_out[((j + 128) * 4 + k) * HH + h];
        bias2 = *(const float4*)(b_out + (j + 128) * 4);
    } else {
        bias2 = make_float4(0.f, 0.f, 0.f, 0.f);
#pragma unroll
        for (int k = 0; k < 4; k++)
#pragma unroll
            for (int h = 0; h < HH; h++)
                w2[k][h] = 0.f;
    }

    const int ntiles = B * SEG * LC;

    // ---- pass 1: masked tiles (pure store stream, no dependencies) ----
    for (;;) {
        if (j == 0) s_tk[slot] = atomicAdd(&g_tkt[0], 1);
        team_bar(barid);
        const int tl = s_tk[slot];
        team_bar(barid);
        if (tl >= ntiles) break;

        const int cc  = tl / (SEG * B);
        const int r   = tl % (SEG * B);
        const int seg = r / B;
        const int b   = r % B;
        const int t0  = (seg * LC + cc) * CH;
        const int len = is64l ? (int)((const long long*)lengthsv)[b] : l32[b];
        if (len > t0) continue;                 // live: handled in pass 2

        const int rows = min(CH, T - t0);
        float* base = out + ((size_t)b * T + t0) * O;
#pragma unroll 4
        for (int rr = 0; rr < rows; rr++) {
            store_cs(base + (size_t)rr * O + j * 4, bias1);
            if (two) store_cs(base + (size_t)rr * O + (j + 128) * 4, bias2);
        }
    }

    // ---- pass 2: live tiles (flag-gated) ----
    for (;;) {
        if (j == 0) s_tk[slot] = atomicAdd(&g_tkt[1], 1);
        team_bar(barid);
        const int tl = s_tk[slot];
        team_bar(barid);
        if (tl >= ntiles) break;

        const int cc  = tl / (SEG * B);
        const int r   = tl % (SEG * B);
        const int seg = r / B;
        const int b   = r % B;
        const int t0  = (seg * LC + cc) * CH;
        const int len = is64l ? (int)((const long long*)lengthsv)[b] : l32[b];
        if (len <= t0) continue;                // masked: done in pass 1

        // every thread spins independently (release/acquire pair with producer)
        while (load_acquire_gpu(&g_flags[b * SEG + seg]) <= cc) __nanosleep(64);

        const int rows = min(CH, T - t0);
        const int rlim = min(rows, len - t0);
        const float4* hsv = (const float4*)(g_hs + ((size_t)b * T + t0) * HH);
        float* base = out + ((size_t)b * T + t0) * O;

        for (int rr = 0; rr < rlim; rr++) {
            const float4 ha = __ldg(hsv + rr * 2);
            const float4 hb = __ldg(hsv + rr * 2 + 1);
            store_cs(base + (size_t)rr * O + j * 4, proj_row4(ha, hb, w1, bias1));
            if (two)
                store_cs(base + (size_t)rr * O + (j + 128) * 4, proj_row4(ha, hb, w2, bias2));
        }
#pragma unroll 4
        for (int rr = rlim; rr < rows; rr++) {
            store_cs(base + (size_t)rr * O + j * 4, bias1);
            if (two) store_cs(base + (size_t)rr * O + (j + 128) * 4, bias2);
        }
    }
}

__global__ void __launch_bounds__(256, 1)
rnn_fused_kernel(const void* __restrict__ Xv,
                 const void* __restrict__ lengthsv,
                 const float* __restrict__ emb,
                 const float* __restrict__ W_ih,
                 const float* __restrict__ W_hh,
                 const float* __restrict__ b_ih,
                 const float* __restrict__ b_hh,
                 const float* __restrict__ W_out,
                 const float* __restrict__ b_out,
                 float* __restrict__ out,
                 int B, int T, int V, int O, int tail)
{
    const int bid = blockIdx.x;
    const int tid = threadIdx.x;
    const int L   = T / SEG;            // 512
    const int LC  = L / CH;             // 8 chunks per segment

    __shared__ int s_tk[2];             // team ticket broadcast slots

    if (bid < B) {
        // =================== recurrence block (seq b = bid) ===================
        float* s_embproj = (float*)dsmem;                   // V*HH floats
        int*   s_tok     = (int*)(dsmem + MAX_V * HH * 4);  // T+2 ints
        __shared__ int s_is64;

        {   // inline dtype detect on X: int64 (<2^31) => odd words all zero
            const int* x32 = (const int*)Xv;
            const int pairs = min(1024, (B * T) >> 1);
            int nz = 0;
            for (int i = tid; i < pairs; i += blockDim.x)
                nz |= (x32[2 * i + 1] != 0);
            const int any = __syncthreads_or(nz);
            if (tid == 0) s_is64 = !any;
            __syncthreads();
        }
        const int is64 = s_is64;

        // --- stage this sequence's full token stream ---
        if (is64) {
            const long long* X = (const long long*)Xv;
            for (int t = tid; t < T; t += blockDim.x) {
                int v = (int)X[(long long)bid * T + t];
                s_tok[t] = min(max(v, 0), V - 1);
            }
        } else {
            const int* X = (const int*)Xv;
            for (int t = tid; t < T; t += blockDim.x) {
                int v = X[bid * T + t];
                s_tok[t] = min(max(v, 0), V - 1);
            }
        }
        if (tid < 2) s_tok[T + tid] = 0;

        // --- embedding projection with both biases folded in ---
        for (int v = tid; v < V; v += blockDim.x) {
            float e[HH];
#pragma unroll
            for (int h = 0; h < HH; h++) e[h] = emb[v * HH + h];
#pragma unroll
            for (int i = 0; i < HH; i++) {
                float s = b_ih[i] + b_hh[i];
#pragma unroll
                for (int h = 0; h < HH; h++)
                    s = fmaf(e[h], W_ih[i * HH + h], s);
                s_embproj[v * HH + i] = s;
            }
        }
        __syncthreads();

        // ---- warps 4-7: project IMMEDIATELY (team slot 1, barrier 2) ----
        if (tid >= 128) {
            proj_team(W_out, b_out, lengthsv, out, B, T, O, LC, s_tk);
            return;
        }

        // ---- warps 0-3: recurrence (bit-exact R14 path) ----
        {
            const int seg  = tid >> 5;          // this warp's segment
            const int lane = tid & 31;
            const int i    = lane & 7;

            const float w0 = W_hh[i * HH + 0], w1 = W_hh[i * HH + 1];
            const float w2 = W_hh[i * HH + 2], w3 = W_hh[i * HH + 3];
            const float w4 = W_hh[i * HH + 4], w5 = W_hh[i * HH + 5];
            const float w6 = W_hh[i * HH + 6], w7 = W_hh[i * HH + 7];

            float h0 = 0.f, h1 = 0.f, h2 = 0.f, h3 = 0.f;
            float h4 = 0.f, h5 = 0.f, h6 = 0.f, h7 = 0.f;

            float* __restrict__ hs_out = g_hs + (size_t)bid * T * HH;
            const int* __restrict__ tok = s_tok;

            const int tout = seg * L;                       // first emitted step
            const int tw   = (seg == 0) ? 0 : tout - WARM;  // warmup start

            int   tokB = tok[tw + 1];
            float xp   = s_embproj[tok[tw] * HH + i];

            // warmup: champion step without store
#pragma unroll 4
            for (int t = tw; t < tout; t++) {
                const int   tokC = tok[t + 2];
                const float xp_n = s_embproj[tokB * HH + i];
                float a = fmaf(h0, w0, xp);
                a = fmaf(h1, w1, a);
                a = fmaf(h2, w2, a);
                a = fmaf(h3, w3, a);
                float bb = h4 * w4;
                bb = fmaf(h5, w5, bb);
                bb = fmaf(h6, w6, bb);
                bb = fmaf(h7, w7, bb);
                const float y = fast_tanh(a + bb);
                h0 = __shfl_sync(0xffffffffu, y, 0);
                h1 = __shfl_sync(0xffffffffu, y, 1);
                h2 = __shfl_sync(0xffffffffu, y, 2);
                h3 = __shfl_sync(0xffffffffu, y, 3);
                h4 = __shfl_sync(0xffffffffu, y, 4);
                h5 = __shfl_sync(0xffffffffu, y, 5);
                h6 = __shfl_sync(0xffffffffu, y, 6);
                h7 = __shfl_sync(0xffffffffu, y, 7);
                xp   = xp_n;
                tokB = tokC;
            }

            // emit: champion chunk loop with per-chunk publish
            for (int cc = 0; cc < LC; cc++) {
                const int t0 = tout + cc * CH;
#pragma unroll 4
                for (int t = t0; t < t0 + CH; t++) {
                    const int   tokC = tok[t + 2];
                    const float xp_n = s_embproj[tokB * HH + i];
                    float a = fmaf(h0, w0, xp);
                    a = fmaf(h1, w1, a);
                    a = fmaf(h2, w2, a);
                    a = fmaf(h3, w3, a);
                    float bb = h4 * w4;
                    bb = fmaf(h5, w5, bb);
                    bb = fmaf(h6, w6, bb);
                    bb = fmaf(h7, w7, bb);
                    const float y = fast_tanh(a + bb);
                    if (lane < HH) hs_out[t * HH + lane] = y;
                    h0 = __shfl_sync(0xffffffffu, y, 0);
                    h1 = __shfl_sync(0xffffffffu, y, 1);
                    h2 = __shfl_sync(0xffffffffu, y, 2);
                    h3 = __shfl_sync(0xffffffffu, y, 3);
                    h4 = __shfl_sync(0xffffffffu, y, 4);
                    h5 = __shfl_sync(0xffffffffu, y, 5);
                    h6 = __shfl_sync(0xffffffffu, y, 6);
                    h7 = __shfl_sync(0xffffffffu, y, 7);
                    xp   = xp_n;
                    tokB = tokC;
                }
                __syncwarp();
                if (lane == 0) {
                    __threadfence();
                    *(volatile int*)&g_flags[bid * SEG + seg] = cc + 1;
                }
            }
        }

        // rec warps (tid<128) join as team slot 0 (barrier 1)
        proj_team(W_out, b_out, lengthsv, out, B, T, O, LC, s_tk);
        return;
    }

    // =================== projection-dedicated blocks ===================
    // tail passthrough handled once (all 256 threads of block B, no sync needed)
    if (bid == B && tail > 0) {
        const int* l32 = (const int*)lengthsv;
        int nzl = 0;
        for (int k = 1; k < B; k += 2) nzl |= (l32[k] != 0);
        const int is64l = !nzl;
        const long long base = (long long)B * T * O;
        if (tail == 2 * B) {
            if (tid < B) {
                long long lv = is64l ? ((const long long*)lengthsv)[tid]
                                     : (long long)l32[tid];
                ((long long*)(out + base))[tid] = lv;
            }
        } else {
            for (int k = tid; k < tail; k += 256) {
                float v = 0.0f;
                if (k < B)
                    v = (float)(is64l ? ((const long long*)lengthsv)[k]
                                      : (long long)l32[k]);
                out[base + k] = v;
            }
        }
    }

    proj_team(W_out, b_out, lengthsv, out, B, T, O, LC, s_tk);
}

extern "C" void kernel_launch(void* const* d_in, const int* in_sizes, int n_in,
                              void* d_out, int out_size)
{
    const void*  X       = d_in[0];
    const void*  lengths = d_in[1];
    const float* emb     = (const float*)d_in[2];
    const float* W_ih    = (const float*)d_in[3];
    const float* W_hh    = (const float*)d_in[4];
    const float* b_ih    = (const float*)d_in[5];
    const float* b_hh    = (const float*)d_in[6];
    const float* W_out   = (const float*)d_in[7];
    const float* b_out   = (const float*)d_in[8];
    float*       out     = (float*)d_out;

    const int B  = in_sizes[1];
    const int BT = in_sizes[0];
    const int T  = BT / B;
    const int H  = in_sizes[5];
    const int V  = in_sizes[2] / H;
    const int O  = in_sizes[8];

    const long long tail = (long long)out_size - (long long)BT * O;

    const int smemBytes = MAX_V * HH * 4 + (MAX_T + 2) * 4;   // ~40 KB dynamic
    cudaFuncSetAttribute(rnn_fused_kernel,
                         cudaFuncAttributeMaxDynamicSharedMemorySize,
                         smemBytes);

    void* flagAddr = nullptr;
    cudaGetSymbolAddress(&flagAddr, g_flags);
    cudaMemsetAsync(flagAddr, 0, sizeof(int) * MAX_B * SEG);
    void* tktAddr = nullptr;
    cudaGetSymbolAddress(&tktAddr, g_tkt);
    cudaMemsetAsync(tktAddr, 0, sizeof(int) * 2);

    rnn_fused_kernel<<<GRID, 256, smemBytes>>>(X, lengths, emb, W_ih, W_hh,
                                               b_ih, b_hh, W_out, b_out, out,
                                               B, T, V, O,
                                               (int)(tail > 0 ? tail : 0));
}